// round 10
// baseline (speedup 1.0000x reference)
#include <cuda_runtime.h>
#include <cuda_fp16.h>
#include <cstdint>

#define NN 50000
#define FIN 256
#define NH 64
#define EMAX 800000
#define SCAN_B 196            // blocks per view in scan (196*256 >= 50000)

// Scratch (allocation-free rule: __device__ globals)
__device__ __half g_xwh[3 * NN * NH];   // x @ W1 per view (fp16 storage)
__device__ float g_degc[3 * NN * 2];    // interleaved {weighted deg, count} (zeroed by scanC)
__device__ int   g_off[3 * (NN + 1)];   // CSR offsets per view
__device__ int   g_cur[3 * NN];         // fill cursors
__device__ int2  g_csr[3 * EMAX];       // CSR: {src, float_bits(norm)} per in-edge
__device__ int   g_bsum[3 * SCAN_B];    // per-block count totals
__device__ int   g_bflag[3 * SCAN_B];   // publish flags (zeroed by k_deg each call)
__device__ float g_dinv1[3 * NN];
__device__ float g_dinv2[3 * NN];
__device__ float g_hws[3 * NN];         // (h @ W2) * dinv2

__device__ __forceinline__ void red_v2(float* p, float a, float b) {
    asm volatile("red.global.add.v2.f32 [%0], {%1,%2};"
                 :: "l"(p), "f"(a), "f"(b) : "memory");
}
__device__ __forceinline__ uint32_t to_tf32(float f) {
    uint32_t r;
    asm("cvt.rna.tf32.f32 %0, %1;" : "=r"(r) : "f"(f));
    return r;
}

// degree histogram; also zeroes scan flags for this call
__global__ void k_deg(const int* __restrict__ e0, const int* __restrict__ e1, const int* __restrict__ e2,
                      const float* __restrict__ w0, const float* __restrict__ w1, const float* __restrict__ w2,
                      int E) {
    if (blockIdx.x < SCAN_B && threadIdx.x == 0)
        g_bflag[blockIdx.y * SCAN_B + blockIdx.x] = 0;
    int e = blockIdx.x * blockDim.x + threadIdx.x;
    if (e >= E) return;
    int v = blockIdx.y;
    const int* ei = v == 0 ? e0 : v == 1 ? e1 : e2;
    const float* ew = v == 0 ? w0 : v == 1 ? w1 : w2;
    int d = ei[E + e];
    red_v2(&g_degc[(v * NN + d) * 2], ew[e], 1.f);
}

// single-pass scan with decoupled (aggregate-only) lookback:
// local exclusive scan, publish block total, sum predecessor totals, write
// off/cur/dinv1/dinv2, and re-zero g_degc for the next replay.
__global__ void k_scanC(int E) {
    __shared__ int sm[256];
    __shared__ int swarp[8];
    __shared__ int sbase;
    int v = blockIdx.y;
    int b = blockIdx.x;
    int idx = b * 256 + threadIdx.x;
    int t = threadIdx.x;

    float dw = 0.f;
    int c = 0;
    if (idx < NN) {
        dw = g_degc[(v * NN + idx) * 2 + 0];
        c  = (int)g_degc[(v * NN + idx) * 2 + 1];
        g_degc[(v * NN + idx) * 2 + 0] = 0.f;   // cleanup for next replay
        g_degc[(v * NN + idx) * 2 + 1] = 0.f;
    }
    sm[t] = c;
    __syncthreads();
    for (int o = 1; o < 256; o <<= 1) {
        int y = (t >= o) ? sm[t - o] : 0;
        __syncthreads();
        if (t >= o) sm[t] += y;
        __syncthreads();
    }
    // publish block total ASAP
    if (t == 0) {
        g_bsum[v * SCAN_B + b] = sm[255];
        __threadfence();
        atomicExch(&g_bflag[v * SCAN_B + b], 1);
    }
    // lookback: thread t waits on predecessor t's aggregate
    int part = 0;
    if (t < b) {
        while (atomicAdd(&g_bflag[v * SCAN_B + t], 0) == 0) {}
        __threadfence();
        part = g_bsum[v * SCAN_B + t];
    }
#pragma unroll
    for (int o = 16; o > 0; o >>= 1) part += __shfl_xor_sync(0xFFFFFFFFu, part, o);
    if ((t & 31) == 0) swarp[t >> 5] = part;
    __syncthreads();
    if (t == 0) {
        int s = 0;
#pragma unroll
        for (int i = 0; i < 8; i++) s += swarp[i];
        sbase = s;
    }
    __syncthreads();
    if (idx < NN) {
        int off = sbase + sm[t] - c;    // exclusive
        g_off[v * (NN + 1) + idx] = off;
        g_cur[v * NN + idx] = off;
        g_dinv1[v * NN + idx] = rsqrtf(1.f + dw);
        g_dinv2[v * NN + idx] = rsqrtf(1.f + (float)c);
    }
    if (b == 0 && t == 0) g_off[v * (NN + 1) + NN] = E;
}

// CSR fill: packed {src, norm}
__global__ void k_fill(const int* __restrict__ e0, const int* __restrict__ e1, const int* __restrict__ e2,
                       const float* __restrict__ w0, const float* __restrict__ w1, const float* __restrict__ w2,
                       int E) {
    int e = blockIdx.x * blockDim.x + threadIdx.x;
    if (e >= E) return;
    int v = blockIdx.y;
    const int* ei = v == 0 ? e0 : v == 1 ? e1 : e2;
    const float* ew = v == 0 ? w0 : v == 1 ? w1 : w2;
    int s = ei[e];
    int d = ei[E + e];
    int pos = atomicAdd(&g_cur[v * NN + d], 1);
    float nrm = g_dinv1[v * NN + s] * ew[e] * g_dinv1[v * NN + d];
    g_csr[v * EMAX + pos] = make_int2(s, __float_as_int(nrm));
}

// xw = x @ W1 for all 3 views via tf32 mma.sync.m16n8k8; fp16 output.
__global__ void k_gemm3(const float* __restrict__ x,
                        const float* __restrict__ W1a, const float* __restrict__ W1b,
                        const float* __restrict__ W1c) {
    int v = blockIdx.y;
    const float* W = v == 0 ? W1a : v == 1 ? W1b : W1c;
    __shared__ uint32_t xs[128][36];   // [row][k] tf32
    __shared__ uint32_t ws[32][68];    // [k][col] tf32
    int tid  = threadIdx.x;
    int wid  = tid >> 5;
    int lane = tid & 31;
    int g = lane >> 2;
    int t = lane & 3;
    int row0 = blockIdx.x * 128;
    int wr = wid * 16;

    float c[8][4];
#pragma unroll
    for (int nt = 0; nt < 8; nt++)
#pragma unroll
        for (int i = 0; i < 4; i++) c[nt][i] = 0.f;

    for (int kc = 0; kc < FIN; kc += 32) {
#pragma unroll
        for (int j = 0; j < 4; j++) {
            int idx = tid + j * 256;
            int r = idx >> 3, f4 = idx & 7;
            int gr = row0 + r;
            float4 xv = make_float4(0.f, 0.f, 0.f, 0.f);
            if (gr < NN) xv = *(const float4*)&x[gr * FIN + kc + f4 * 4];
            uint32_t* p = &xs[r][f4 * 4];
            p[0] = to_tf32(xv.x); p[1] = to_tf32(xv.y);
            p[2] = to_tf32(xv.z); p[3] = to_tf32(xv.w);
        }
#pragma unroll
        for (int j = 0; j < 2; j++) {
            int idx = tid + j * 256;
            int kr = idx >> 4, c4 = idx & 15;
            float4 wv = *(const float4*)&W[(kc + kr) * NH + c4 * 4];
            uint32_t* p = &ws[kr][c4 * 4];
            p[0] = to_tf32(wv.x); p[1] = to_tf32(wv.y);
            p[2] = to_tf32(wv.z); p[3] = to_tf32(wv.w);
        }
        __syncthreads();
#pragma unroll
        for (int k0 = 0; k0 < 32; k0 += 8) {
            uint32_t a0 = xs[wr + g][k0 + t];
            uint32_t a1 = xs[wr + g + 8][k0 + t];
            uint32_t a2 = xs[wr + g][k0 + t + 4];
            uint32_t a3 = xs[wr + g + 8][k0 + t + 4];
#pragma unroll
            for (int nt = 0; nt < 8; nt++) {
                uint32_t b0 = ws[k0 + t][nt * 8 + g];
                uint32_t b1 = ws[k0 + t + 4][nt * 8 + g];
                asm volatile(
                    "mma.sync.aligned.m16n8k8.row.col.f32.tf32.tf32.f32 "
                    "{%0,%1,%2,%3}, {%4,%5,%6,%7}, {%8,%9}, {%0,%1,%2,%3};"
                    : "+f"(c[nt][0]), "+f"(c[nt][1]), "+f"(c[nt][2]), "+f"(c[nt][3])
                    : "r"(a0), "r"(a1), "r"(a2), "r"(a3), "r"(b0), "r"(b1));
            }
        }
        __syncthreads();
    }
    size_t vb = (size_t)v * NN * NH;
    int r0 = row0 + wr + g;
    int r1 = r0 + 8;
#pragma unroll
    for (int nt = 0; nt < 8; nt++) {
        int col = nt * 8 + t * 2;
        if (r0 < NN) *(__half2*)&g_xwh[vb + (size_t)r0 * NH + col] = __floats2half2_rn(c[nt][0], c[nt][1]);
        if (r1 < NN) *(__half2*)&g_xwh[vb + (size_t)r1 * NH + col] = __floats2half2_rn(c[nt][2], c[nt][3]);
    }
}

// conv1 pull + epilogue: ONE WARP PER NODE.
// lane = (sub 0..3) * 8 + q; sub indexes edges (stride 4), q the 16B feature chunk.
__global__ void k_gather1(const float* __restrict__ b1a, const float* __restrict__ b1b, const float* __restrict__ b1c,
                          const float* __restrict__ W2a, const float* __restrict__ W2b, const float* __restrict__ W2c,
                          float* __restrict__ out_feat) {
    int gtid = blockIdx.x * blockDim.x + threadIdx.x;
    int node = gtid >> 5;
    if (node >= NN) return;
    int lane = threadIdx.x & 31;
    int q   = lane & 7;
    int sub = lane >> 3;

    float fo[8];
#pragma unroll
    for (int i = 0; i < 8; i++) fo[i] = 0.f;
    float dot[3];
#pragma unroll
    for (int v = 0; v < 3; v++) {
        const float* b1 = v == 0 ? b1a : v == 1 ? b1b : b1c;
        const float* W2 = v == 0 ? W2a : v == 1 ? W2b : W2c;
        int beg = g_off[v * (NN + 1) + node];
        int end = g_off[v * (NN + 1) + node + 1];
        const int2* cp = g_csr + v * EMAX;
        const uint4* xw8 = (const uint4*)(g_xwh + (size_t)v * NN * NH);
        float a[8];
#pragma unroll
        for (int i = 0; i < 8; i++) a[i] = 0.f;
#pragma unroll 2
        for (int j = beg + sub; j < end; j += 4) {
            int2 m = cp[j];
            float nm = __int_as_float(m.y);
            uint4 raw = xw8[(size_t)m.x * 8 + q];
            float2 f0 = __half22float2(*(__half2*)&raw.x);
            float2 f1 = __half22float2(*(__half2*)&raw.y);
            float2 f2 = __half22float2(*(__half2*)&raw.z);
            float2 f3 = __half22float2(*(__half2*)&raw.w);
            a[0] += nm * f0.x; a[1] += nm * f0.y;
            a[2] += nm * f1.x; a[3] += nm * f1.y;
            a[4] += nm * f2.x; a[5] += nm * f2.y;
            a[6] += nm * f3.x; a[7] += nm * f3.y;
        }
        // reduce over the 4 edge-subgroups (lanes q, q+8, q+16, q+24)
#pragma unroll
        for (int i = 0; i < 8; i++) {
            a[i] += __shfl_xor_sync(0xFFFFFFFFu, a[i], 8);
            a[i] += __shfl_xor_sync(0xFFFFFFFFu, a[i], 16);
        }
        // self loop + bias + relu + dot (computed redundantly in each sub, harmless)
        float di = g_dinv1[v * NN + node];
        float sn = di * di;
        uint4 sr = xw8[(size_t)node * 8 + q];
        float2 s0 = __half22float2(*(__half2*)&sr.x);
        float2 s1 = __half22float2(*(__half2*)&sr.y);
        float2 s2 = __half22float2(*(__half2*)&sr.z);
        float2 s3 = __half22float2(*(__half2*)&sr.w);
        float sf[8] = {s0.x, s0.y, s1.x, s1.y, s2.x, s2.y, s3.x, s3.y};
        float4 bva = *(const float4*)&b1[q * 8];
        float4 bvb = *(const float4*)&b1[q * 8 + 4];
        float bv[8] = {bva.x, bva.y, bva.z, bva.w, bvb.x, bvb.y, bvb.z, bvb.w};
        float4 w2a = *(const float4*)&W2[q * 8];
        float4 w2b = *(const float4*)&W2[q * 8 + 4];
        float w2[8] = {w2a.x, w2a.y, w2a.z, w2a.w, w2b.x, w2b.y, w2b.z, w2b.w};
        float dt = 0.f;
#pragma unroll
        for (int i = 0; i < 8; i++) {
            float hv = fmaxf(a[i] + sf[i] * sn + bv[i], 0.f);
            fo[i] += hv;
            dt += hv * w2[i];
        }
        dot[v] = dt;
    }
    // reduce dot over the 8 q-lanes within each sub-octet
#pragma unroll
    for (int o = 4; o > 0; o >>= 1) {
        dot[0] += __shfl_xor_sync(0xFFFFFFFFu, dot[0], o);
        dot[1] += __shfl_xor_sync(0xFFFFFFFFu, dot[1], o);
        dot[2] += __shfl_xor_sync(0xFFFFFFFFu, dot[2], o);
    }
    if (lane == 0) {
#pragma unroll
        for (int v = 0; v < 3; v++)
            g_hws[v * NN + node] = dot[v] * g_dinv2[v * NN + node];
    }
    if (sub == 0) {
        *(float4*)&out_feat[node * NH + q * 8]     = make_float4(fo[0], fo[1], fo[2], fo[3]);
        *(float4*)&out_feat[node * NH + q * 8 + 4] = make_float4(fo[4], fo[5], fo[6], fo[7]);
    }
}

// conv2 pull
__global__ void k_gather2(const float* __restrict__ b2a, const float* __restrict__ b2b, const float* __restrict__ b2c,
                          float* __restrict__ out) {
    int i = blockIdx.x * blockDim.x + threadIdx.x;
    if (i >= NN) return;
    float acc = 0.f;
#pragma unroll
    for (int v = 0; v < 3; v++) {
        const float* b2 = v == 0 ? b2a : v == 1 ? b2b : b2c;
        int beg = g_off[v * (NN + 1) + i];
        int end = g_off[v * (NN + 1) + i + 1];
        const int2* cp = g_csr + v * EMAX;
        float t = 0.f;
#pragma unroll 8
        for (int j = beg; j < end; j++)
            t += g_hws[v * NN + cp[j].x];
        float di = g_dinv2[v * NN + i];
        acc += di * t + g_hws[v * NN + i] * di + b2[0];
    }
    out[i] = acc;
}

extern "C" void kernel_launch(void* const* d_in, const int* in_sizes, int n_in,
                              void* d_out, int out_size) {
    const float* x = (const float*)d_in[0];
    const int* e0 = (const int*)d_in[1];
    const int* e1 = (const int*)d_in[2];
    const int* e2 = (const int*)d_in[3];
    const float* w0 = (const float*)d_in[4];
    const float* w1 = (const float*)d_in[5];
    const float* w2 = (const float*)d_in[6];
    const float* W1a = (const float*)d_in[7];
    const float* b1a = (const float*)d_in[8];
    const float* W2a = (const float*)d_in[9];
    const float* b2a = (const float*)d_in[10];
    const float* W1b = (const float*)d_in[11];
    const float* b1b = (const float*)d_in[12];
    const float* W2b = (const float*)d_in[13];
    const float* b2b = (const float*)d_in[14];
    const float* W1c = (const float*)d_in[15];
    const float* b1c = (const float*)d_in[16];
    const float* W2c = (const float*)d_in[17];
    const float* b2c = (const float*)d_in[18];
    float* out = (float*)d_out;
    int E = in_sizes[4];

    // One-time stream/event setup (host-side only; no device memory).
    static cudaStream_t s2 = nullptr;
    static cudaEvent_t evFork = nullptr, evGemm = nullptr;
    if (s2 == nullptr) {
        cudaStreamCreateWithFlags(&s2, cudaStreamNonBlocking);
        cudaEventCreateWithFlags(&evFork, cudaEventDisableTiming);
        cudaEventCreateWithFlags(&evGemm, cudaEventDisableTiming);
    }

    // Fork: GEMM runs on s2 concurrently with the CSR-build chain.
    cudaEventRecord(evFork, 0);
    cudaStreamWaitEvent(s2, evFork, 0);
    dim3 ggemm((NN + 127) / 128, 3);
    k_gemm3<<<ggemm, 256, 0, s2>>>(x, W1a, W1b, W1c);
    cudaEventRecord(evGemm, s2);

    // Edge pipeline on legacy stream
    dim3 gedge((E + 255) / 256, 3);
    k_deg<<<gedge, 256>>>(e0, e1, e2, w0, w1, w2, E);

    dim3 gscan(SCAN_B, 3);
    k_scanC<<<gscan, 256>>>(E);

    k_fill<<<gedge, 256>>>(e0, e1, e2, w0, w1, w2, E);

    // Join: gather1 needs both the CSR and g_xwh
    cudaStreamWaitEvent(0, evGemm, 0);

    k_gather1<<<(NN * 32 + 255) / 256, 256>>>(b1a, b1b, b1c, W2a, W2b, W2c, out + NN);

    k_gather2<<<(NN + 255) / 256, 256>>>(b2a, b2b, b2c, out);
}

// round 13
// speedup vs baseline: 1.1309x; 1.1309x over previous
#include <cuda_runtime.h>
#include <cuda_fp16.h>
#include <cstdint>

#define NN 50000
#define FIN 256
#define NH 64
#define EMAX 800000
#define SCAN_B 196            // blocks per view in hierarchical scan (196*256 >= 50000)

// Scratch (allocation-free rule: __device__ globals)
__device__ __half g_xwh[3 * NN * NH];   // x @ W1 per view (fp16 storage)
__device__ float g_degc[3 * NN * 2];    // interleaved {weighted deg, count} (zeroed by scanC)
__device__ int   g_off[3 * (NN + 1)];   // CSR offsets per view
__device__ int   g_cur[3 * NN];         // fill cursors
__device__ int2  g_csr[3 * EMAX];       // CSR: {src, float_bits(dinv1[src]*w)} per in-edge
__device__ int   g_bsum[3 * SCAN_B];    // per-block count sums (scan level 1)
__device__ float g_dinv1[3 * NN];
__device__ float g_dinv2[3 * NN];
__device__ float g_hws[3 * NN];         // (h @ W2) * dinv2

__device__ __forceinline__ void red_v2(float* p, float a, float b) {
    asm volatile("red.global.add.v2.f32 [%0], {%1,%2};"
                 :: "l"(p), "f"(a), "f"(b) : "memory");
}
__device__ __forceinline__ uint32_t to_tf32(float f) {
    uint32_t r;
    asm("cvt.rna.tf32.f32 %0, %1;" : "=r"(r) : "f"(f));
    return r;
}

// degree histogram (g_degc pre-zeroed: first run static init, then scanC cleanup)
__global__ void k_deg(const int* __restrict__ e0, const int* __restrict__ e1, const int* __restrict__ e2,
                      const float* __restrict__ w0, const float* __restrict__ w1, const float* __restrict__ w2,
                      int E) {
    int e = blockIdx.x * blockDim.x + threadIdx.x;
    if (e >= E) return;
    int v = blockIdx.y;
    const int* ei = v == 0 ? e0 : v == 1 ? e1 : e2;
    const float* ew = v == 0 ? w0 : v == 1 ? w1 : w2;
    int d = ei[E + e];
    red_v2(&g_degc[(v * NN + d) * 2], ew[e], 1.f);
}

// scan level 1: per-block (256-node) count sums, coalesced
__global__ void k_scanA() {
    __shared__ int sm[8];
    int v = blockIdx.y;
    int idx = blockIdx.x * 256 + threadIdx.x;
    int c = (idx < NN) ? (int)g_degc[(v * NN + idx) * 2 + 1] : 0;
#pragma unroll
    for (int o = 16; o > 0; o >>= 1) c += __shfl_xor_sync(0xFFFFFFFFu, c, o);
    if ((threadIdx.x & 31) == 0) sm[threadIdx.x >> 5] = c;
    __syncthreads();
    if (threadIdx.x == 0) {
        int s = 0;
#pragma unroll
        for (int i = 0; i < 8; i++) s += sm[i];
        g_bsum[v * SCAN_B + blockIdx.x] = s;
    }
}

// scan level 2: per-block base via reduce of preceding block sums, local scan,
// write off/cur/dinv1/dinv2, re-zero g_degc for next replay.
__global__ void k_scanC(int E) {
    __shared__ int sm[256];
    __shared__ int swarp[8];
    __shared__ int sbase;
    int v = blockIdx.y;
    int idx = blockIdx.x * 256 + threadIdx.x;
    int t = threadIdx.x;

    int bv = (t < blockIdx.x && t < SCAN_B) ? g_bsum[v * SCAN_B + t] : 0;
#pragma unroll
    for (int o = 16; o > 0; o >>= 1) bv += __shfl_xor_sync(0xFFFFFFFFu, bv, o);
    if ((t & 31) == 0) swarp[t >> 5] = bv;
    __syncthreads();
    if (t == 0) {
        int s = 0;
#pragma unroll
        for (int i = 0; i < 8; i++) s += swarp[i];
        sbase = s;
    }

    float dw = 0.f;
    int c = 0;
    if (idx < NN) {
        dw = g_degc[(v * NN + idx) * 2 + 0];
        c  = (int)g_degc[(v * NN + idx) * 2 + 1];
        g_degc[(v * NN + idx) * 2 + 0] = 0.f;
        g_degc[(v * NN + idx) * 2 + 1] = 0.f;
    }
    sm[t] = c;
    __syncthreads();
    for (int o = 1; o < 256; o <<= 1) {
        int y = (t >= o) ? sm[t - o] : 0;
        __syncthreads();
        if (t >= o) sm[t] += y;
        __syncthreads();
    }
    if (idx < NN) {
        int off = sbase + sm[t] - c;    // exclusive
        g_off[v * (NN + 1) + idx] = off;
        g_cur[v * NN + idx] = off;
        g_dinv1[v * NN + idx] = rsqrtf(1.f + dw);
        g_dinv2[v * NN + idx] = rsqrtf(1.f + (float)c);
    }
    if (blockIdx.x == 0 && t == 0) g_off[v * (NN + 1) + NN] = E;
}

// CSR fill: packed {src, dinv1[src]*w}. dinv1[dst] factored out (applied in gather1).
__global__ void k_fill(const int* __restrict__ e0, const int* __restrict__ e1, const int* __restrict__ e2,
                       const float* __restrict__ w0, const float* __restrict__ w1, const float* __restrict__ w2,
                       int E) {
    int e = blockIdx.x * blockDim.x + threadIdx.x;
    if (e >= E) return;
    int v = blockIdx.y;
    const int* ei = v == 0 ? e0 : v == 1 ? e1 : e2;
    const float* ew = v == 0 ? w0 : v == 1 ? w1 : w2;
    int s = ei[e];
    int d = ei[E + e];
    int pos = atomicAdd(&g_cur[v * NN + d], 1);
    float part = g_dinv1[v * NN + s] * ew[e];
    g_csr[v * EMAX + pos] = make_int2(s, __float_as_int(part));
}

// xw = x @ W1 for all 3 views via tf32 mma.sync.m16n8k8; fp16 output.
__global__ void k_gemm3(const float* __restrict__ x,
                        const float* __restrict__ W1a, const float* __restrict__ W1b,
                        const float* __restrict__ W1c) {
    int v = blockIdx.y;
    const float* W = v == 0 ? W1a : v == 1 ? W1b : W1c;
    __shared__ uint32_t xs[128][36];   // [row][k] tf32
    __shared__ uint32_t ws[32][68];    // [k][col] tf32
    int tid  = threadIdx.x;
    int wid  = tid >> 5;
    int lane = tid & 31;
    int g = lane >> 2;
    int t = lane & 3;
    int row0 = blockIdx.x * 128;
    int wr = wid * 16;

    float c[8][4];
#pragma unroll
    for (int nt = 0; nt < 8; nt++)
#pragma unroll
        for (int i = 0; i < 4; i++) c[nt][i] = 0.f;

    for (int kc = 0; kc < FIN; kc += 32) {
#pragma unroll
        for (int j = 0; j < 4; j++) {
            int idx = tid + j * 256;
            int r = idx >> 3, f4 = idx & 7;
            int gr = row0 + r;
            float4 xv = make_float4(0.f, 0.f, 0.f, 0.f);
            if (gr < NN) xv = *(const float4*)&x[gr * FIN + kc + f4 * 4];
            uint32_t* p = &xs[r][f4 * 4];
            p[0] = to_tf32(xv.x); p[1] = to_tf32(xv.y);
            p[2] = to_tf32(xv.z); p[3] = to_tf32(xv.w);
        }
#pragma unroll
        for (int j = 0; j < 2; j++) {
            int idx = tid + j * 256;
            int kr = idx >> 4, c4 = idx & 15;
            float4 wv = *(const float4*)&W[(kc + kr) * NH + c4 * 4];
            uint32_t* p = &ws[kr][c4 * 4];
            p[0] = to_tf32(wv.x); p[1] = to_tf32(wv.y);
            p[2] = to_tf32(wv.z); p[3] = to_tf32(wv.w);
        }
        __syncthreads();
#pragma unroll
        for (int k0 = 0; k0 < 32; k0 += 8) {
            uint32_t a0 = xs[wr + g][k0 + t];
            uint32_t a1 = xs[wr + g + 8][k0 + t];
            uint32_t a2 = xs[wr + g][k0 + t + 4];
            uint32_t a3 = xs[wr + g + 8][k0 + t + 4];
#pragma unroll
            for (int nt = 0; nt < 8; nt++) {
                uint32_t b0 = ws[k0 + t][nt * 8 + g];
                uint32_t b1 = ws[k0 + t + 4][nt * 8 + g];
                asm volatile(
                    "mma.sync.aligned.m16n8k8.row.col.f32.tf32.tf32.f32 "
                    "{%0,%1,%2,%3}, {%4,%5,%6,%7}, {%8,%9}, {%0,%1,%2,%3};"
                    : "+f"(c[nt][0]), "+f"(c[nt][1]), "+f"(c[nt][2]), "+f"(c[nt][3])
                    : "r"(a0), "r"(a1), "r"(a2), "r"(a3), "r"(b0), "r"(b1));
            }
        }
        __syncthreads();
    }
    size_t vb = (size_t)v * NN * NH;
    int r0 = row0 + wr + g;
    int r1 = r0 + 8;
#pragma unroll
    for (int nt = 0; nt < 8; nt++) {
        int col = nt * 8 + t * 2;
        if (r0 < NN) *(__half2*)&g_xwh[vb + (size_t)r0 * NH + col] = __floats2half2_rn(c[nt][0], c[nt][1]);
        if (r1 < NN) *(__half2*)&g_xwh[vb + (size_t)r1 * NH + col] = __floats2half2_rn(c[nt][2], c[nt][3]);
    }
}

// conv1 pull + epilogue: 8 lanes per node, 8 fp16 features (one uint4) each.
// h = dinv1[node]*sum(part*xw[src]) + dinv1[node]^2*xw[node] + b1
__global__ void k_gather1(const float* __restrict__ b1a, const float* __restrict__ b1b, const float* __restrict__ b1c,
                          const float* __restrict__ W2a, const float* __restrict__ W2b, const float* __restrict__ W2c,
                          float* __restrict__ out_feat) {
    int gtid = blockIdx.x * blockDim.x + threadIdx.x;
    int node = gtid >> 3;
    if (node >= NN) return;
    int q = threadIdx.x & 7;        // features q*8 .. q*8+7

    float fo[8];
#pragma unroll
    for (int i = 0; i < 8; i++) fo[i] = 0.f;
    float dot[3];
#pragma unroll
    for (int v = 0; v < 3; v++) {
        const float* b1 = v == 0 ? b1a : v == 1 ? b1b : b1c;
        const float* W2 = v == 0 ? W2a : v == 1 ? W2b : W2c;
        int beg = g_off[v * (NN + 1) + node];
        int end = g_off[v * (NN + 1) + node + 1];
        const int2* cp = g_csr + v * EMAX;
        const uint4* xw8 = (const uint4*)(g_xwh + (size_t)v * NN * NH);
        float a[8];
#pragma unroll
        for (int i = 0; i < 8; i++) a[i] = 0.f;
#pragma unroll 4
        for (int j = beg; j < end; j++) {
            int2 m = cp[j];
            float nm = __int_as_float(m.y);
            uint4 raw = xw8[(size_t)m.x * 8 + q];
            float2 f0 = __half22float2(*(__half2*)&raw.x);
            float2 f1 = __half22float2(*(__half2*)&raw.y);
            float2 f2 = __half22float2(*(__half2*)&raw.z);
            float2 f3 = __half22float2(*(__half2*)&raw.w);
            a[0] += nm * f0.x; a[1] += nm * f0.y;
            a[2] += nm * f1.x; a[3] += nm * f1.y;
            a[4] += nm * f2.x; a[5] += nm * f2.y;
            a[6] += nm * f3.x; a[7] += nm * f3.y;
        }
        // self loop + dst-degree factor
        float di = g_dinv1[v * NN + node];
        float sn = di * di;
        uint4 sr = xw8[(size_t)node * 8 + q];
        float2 s0 = __half22float2(*(__half2*)&sr.x);
        float2 s1 = __half22float2(*(__half2*)&sr.y);
        float2 s2 = __half22float2(*(__half2*)&sr.z);
        float2 s3 = __half22float2(*(__half2*)&sr.w);
        float sf[8] = {s0.x, s0.y, s1.x, s1.y, s2.x, s2.y, s3.x, s3.y};
        float4 bva = *(const float4*)&b1[q * 8];
        float4 bvb = *(const float4*)&b1[q * 8 + 4];
        float bv[8] = {bva.x, bva.y, bva.z, bva.w, bvb.x, bvb.y, bvb.z, bvb.w};
        float4 w2a = *(const float4*)&W2[q * 8];
        float4 w2b = *(const float4*)&W2[q * 8 + 4];
        float w2[8] = {w2a.x, w2a.y, w2a.z, w2a.w, w2b.x, w2b.y, w2b.z, w2b.w};
        float dt = 0.f;
#pragma unroll
        for (int i = 0; i < 8; i++) {
            float hv = fmaxf(a[i] * di + sf[i] * sn + bv[i], 0.f);
            fo[i] += hv;
            dt += hv * w2[i];
        }
        dot[v] = dt;
    }
#pragma unroll
    for (int o = 4; o > 0; o >>= 1) {
        dot[0] += __shfl_xor_sync(0xFFFFFFFFu, dot[0], o);
        dot[1] += __shfl_xor_sync(0xFFFFFFFFu, dot[1], o);
        dot[2] += __shfl_xor_sync(0xFFFFFFFFu, dot[2], o);
    }
    if (q == 0) {
#pragma unroll
        for (int v = 0; v < 3; v++)
            g_hws[v * NN + node] = dot[v] * g_dinv2[v * NN + node];
    }
    *(float4*)&out_feat[node * NH + q * 8]     = make_float4(fo[0], fo[1], fo[2], fo[3]);
    *(float4*)&out_feat[node * NH + q * 8 + 4] = make_float4(fo[4], fo[5], fo[6], fo[7]);
}

// conv2 pull
__global__ void k_gather2(const float* __restrict__ b2a, const float* __restrict__ b2b, const float* __restrict__ b2c,
                          float* __restrict__ out) {
    int i = blockIdx.x * blockDim.x + threadIdx.x;
    if (i >= NN) return;
    float acc = 0.f;
#pragma unroll
    for (int v = 0; v < 3; v++) {
        const float* b2 = v == 0 ? b2a : v == 1 ? b2b : b2c;
        int beg = g_off[v * (NN + 1) + i];
        int end = g_off[v * (NN + 1) + i + 1];
        const int2* cp = g_csr + v * EMAX;
        float t = 0.f;
#pragma unroll 8
        for (int j = beg; j < end; j++)
            t += g_hws[v * NN + cp[j].x];
        float di = g_dinv2[v * NN + i];
        acc += di * t + g_hws[v * NN + i] * di + b2[0];
    }
    out[i] = acc;
}

extern "C" void kernel_launch(void* const* d_in, const int* in_sizes, int n_in,
                              void* d_out, int out_size) {
    const float* x = (const float*)d_in[0];
    const int* e0 = (const int*)d_in[1];
    const int* e1 = (const int*)d_in[2];
    const int* e2 = (const int*)d_in[3];
    const float* w0 = (const float*)d_in[4];
    const float* w1 = (const float*)d_in[5];
    const float* w2 = (const float*)d_in[6];
    const float* W1a = (const float*)d_in[7];
    const float* b1a = (const float*)d_in[8];
    const float* W2a = (const float*)d_in[9];
    const float* b2a = (const float*)d_in[10];
    const float* W1b = (const float*)d_in[11];
    const float* b1b = (const float*)d_in[12];
    const float* W2b = (const float*)d_in[13];
    const float* b2b = (const float*)d_in[14];
    const float* W1c = (const float*)d_in[15];
    const float* b1c = (const float*)d_in[16];
    const float* W2c = (const float*)d_in[17];
    const float* b2c = (const float*)d_in[18];
    float* out = (float*)d_out;
    int E = in_sizes[4];

    // One-time stream/event setup (host-side only; no device memory).
    static cudaStream_t s2 = nullptr;
    static cudaEvent_t evFork = nullptr, evGemm = nullptr;
    if (s2 == nullptr) {
        cudaStreamCreateWithFlags(&s2, cudaStreamNonBlocking);
        cudaEventCreateWithFlags(&evFork, cudaEventDisableTiming);
        cudaEventCreateWithFlags(&evGemm, cudaEventDisableTiming);
    }

    // Fork: GEMM runs on s2 concurrently with the CSR-build chain.
    cudaEventRecord(evFork, 0);
    cudaStreamWaitEvent(s2, evFork, 0);
    dim3 ggemm((NN + 127) / 128, 3);
    k_gemm3<<<ggemm, 256, 0, s2>>>(x, W1a, W1b, W1c);
    cudaEventRecord(evGemm, s2);

    // Edge pipeline on legacy stream
    dim3 gedge((E + 255) / 256, 3);
    k_deg<<<gedge, 256>>>(e0, e1, e2, w0, w1, w2, E);

    dim3 gscan(SCAN_B, 3);
    k_scanA<<<gscan, 256>>>();
    k_scanC<<<gscan, 256>>>(E);

    k_fill<<<gedge, 256>>>(e0, e1, e2, w0, w1, w2, E);

    // Join: gather1 needs both the CSR and g_xwh
    cudaStreamWaitEvent(0, evGemm, 0);

    k_gather1<<<(NN * 8 + 255) / 256, 256>>>(b1a, b1b, b1c, W2a, W2b, W2c, out + NN);

    k_gather2<<<(NN + 255) / 256, 256>>>(b2a, b2b, b2c, out);
}

// round 14
// speedup vs baseline: 1.1554x; 1.0217x over previous
#include <cuda_runtime.h>
#include <cuda_fp16.h>
#include <cstdint>

#define NN 50000
#define FIN 256
#define NH 64
#define EMAX 800000
#define SCAN_B 196            // blocks per view in hierarchical scan (196*256 >= 50000)

// Scratch (allocation-free rule: __device__ globals)
__device__ __half g_xwh[3 * NN * NH];       // x @ W1 per view (fp16 storage)
__device__ float g_degc[3 * NN * 2];        // interleaved {weighted deg, count} (zeroed by scanC)
__device__ int   g_off[3 * (NN + 1)];       // CSR offsets per view
__device__ int   g_cur[3 * NN];             // fill cursors
__device__ uint32_t g_csr[3 * EMAX];        // CSR entry: src(16b) | fp16(dinv1[src]*w)<<16
__device__ int   g_bsum[3 * SCAN_B];        // per-block count sums (scan level 1)
__device__ float g_dinv1[3 * NN];
__device__ float g_dinv2[3 * NN];
__device__ float g_hws[3 * NN];             // (h @ W2) * dinv2

__device__ __forceinline__ void red_v2(float* p, float a, float b) {
    asm volatile("red.global.add.v2.f32 [%0], {%1,%2};"
                 :: "l"(p), "f"(a), "f"(b) : "memory");
}
__device__ __forceinline__ uint32_t to_tf32(float f) {
    uint32_t r;
    asm("cvt.rna.tf32.f32 %0, %1;" : "=r"(r) : "f"(f));
    return r;
}

// degree histogram (g_degc pre-zeroed: first run static init, then scanC cleanup)
__global__ void k_deg(const int* __restrict__ e0, const int* __restrict__ e1, const int* __restrict__ e2,
                      const float* __restrict__ w0, const float* __restrict__ w1, const float* __restrict__ w2,
                      int E) {
    int e = blockIdx.x * blockDim.x + threadIdx.x;
    if (e >= E) return;
    int v = blockIdx.y;
    const int* ei = v == 0 ? e0 : v == 1 ? e1 : e2;
    const float* ew = v == 0 ? w0 : v == 1 ? w1 : w2;
    int d = ei[E + e];
    red_v2(&g_degc[(v * NN + d) * 2], ew[e], 1.f);
}

// scan level 1: per-block (256-node) count sums, coalesced
__global__ void k_scanA() {
    __shared__ int sm[8];
    int v = blockIdx.y;
    int idx = blockIdx.x * 256 + threadIdx.x;
    int c = (idx < NN) ? (int)g_degc[(v * NN + idx) * 2 + 1] : 0;
#pragma unroll
    for (int o = 16; o > 0; o >>= 1) c += __shfl_xor_sync(0xFFFFFFFFu, c, o);
    if ((threadIdx.x & 31) == 0) sm[threadIdx.x >> 5] = c;
    __syncthreads();
    if (threadIdx.x == 0) {
        int s = 0;
#pragma unroll
        for (int i = 0; i < 8; i++) s += sm[i];
        g_bsum[v * SCAN_B + blockIdx.x] = s;
    }
}

// scan level 2: per-block base via reduce of preceding block sums, local scan,
// write off/cur/dinv1/dinv2, re-zero g_degc for next replay.
__global__ void k_scanC(int E) {
    __shared__ int sm[256];
    __shared__ int swarp[8];
    __shared__ int sbase;
    int v = blockIdx.y;
    int idx = blockIdx.x * 256 + threadIdx.x;
    int t = threadIdx.x;

    int bv = (t < blockIdx.x && t < SCAN_B) ? g_bsum[v * SCAN_B + t] : 0;
#pragma unroll
    for (int o = 16; o > 0; o >>= 1) bv += __shfl_xor_sync(0xFFFFFFFFu, bv, o);
    if ((t & 31) == 0) swarp[t >> 5] = bv;
    __syncthreads();
    if (t == 0) {
        int s = 0;
#pragma unroll
        for (int i = 0; i < 8; i++) s += swarp[i];
        sbase = s;
    }

    float dw = 0.f;
    int c = 0;
    if (idx < NN) {
        dw = g_degc[(v * NN + idx) * 2 + 0];
        c  = (int)g_degc[(v * NN + idx) * 2 + 1];
        g_degc[(v * NN + idx) * 2 + 0] = 0.f;
        g_degc[(v * NN + idx) * 2 + 1] = 0.f;
    }
    sm[t] = c;
    __syncthreads();
    for (int o = 1; o < 256; o <<= 1) {
        int y = (t >= o) ? sm[t - o] : 0;
        __syncthreads();
        if (t >= o) sm[t] += y;
        __syncthreads();
    }
    if (idx < NN) {
        int off = sbase + sm[t] - c;    // exclusive
        g_off[v * (NN + 1) + idx] = off;
        g_cur[v * NN + idx] = off;
        g_dinv1[v * NN + idx] = rsqrtf(1.f + dw);
        g_dinv2[v * NN + idx] = rsqrtf(1.f + (float)c);
    }
    if (blockIdx.x == 0 && t == 0) g_off[v * (NN + 1) + NN] = E;
}

// CSR fill: 4-byte entry {src:16, fp16(dinv1[src]*w):16}
__global__ void k_fill(const int* __restrict__ e0, const int* __restrict__ e1, const int* __restrict__ e2,
                       const float* __restrict__ w0, const float* __restrict__ w1, const float* __restrict__ w2,
                       int E) {
    int e = blockIdx.x * blockDim.x + threadIdx.x;
    if (e >= E) return;
    int v = blockIdx.y;
    const int* ei = v == 0 ? e0 : v == 1 ? e1 : e2;
    const float* ew = v == 0 ? w0 : v == 1 ? w1 : w2;
    int s = ei[e];
    int d = ei[E + e];
    int pos = atomicAdd(&g_cur[v * NN + d], 1);
    float part = g_dinv1[v * NN + s] * ew[e];
    uint32_t pb = (uint32_t)__half_as_ushort(__float2half_rn(part));
    g_csr[v * EMAX + pos] = (uint32_t)s | (pb << 16);
}

// xw = x @ W1 for all 3 views via tf32 mma.sync.m16n8k8; fp16 output.
__global__ void k_gemm3(const float* __restrict__ x,
                        const float* __restrict__ W1a, const float* __restrict__ W1b,
                        const float* __restrict__ W1c) {
    int v = blockIdx.y;
    const float* W = v == 0 ? W1a : v == 1 ? W1b : W1c;
    __shared__ uint32_t xs[128][36];   // [row][k] tf32
    __shared__ uint32_t ws[32][68];    // [k][col] tf32
    int tid  = threadIdx.x;
    int wid  = tid >> 5;
    int lane = tid & 31;
    int g = lane >> 2;
    int t = lane & 3;
    int row0 = blockIdx.x * 128;
    int wr = wid * 16;

    float c[8][4];
#pragma unroll
    for (int nt = 0; nt < 8; nt++)
#pragma unroll
        for (int i = 0; i < 4; i++) c[nt][i] = 0.f;

    for (int kc = 0; kc < FIN; kc += 32) {
#pragma unroll
        for (int j = 0; j < 4; j++) {
            int idx = tid + j * 256;
            int r = idx >> 3, f4 = idx & 7;
            int gr = row0 + r;
            float4 xv = make_float4(0.f, 0.f, 0.f, 0.f);
            if (gr < NN) xv = *(const float4*)&x[gr * FIN + kc + f4 * 4];
            uint32_t* p = &xs[r][f4 * 4];
            p[0] = to_tf32(xv.x); p[1] = to_tf32(xv.y);
            p[2] = to_tf32(xv.z); p[3] = to_tf32(xv.w);
        }
#pragma unroll
        for (int j = 0; j < 2; j++) {
            int idx = tid + j * 256;
            int kr = idx >> 4, c4 = idx & 15;
            float4 wv = *(const float4*)&W[(kc + kr) * NH + c4 * 4];
            uint32_t* p = &ws[kr][c4 * 4];
            p[0] = to_tf32(wv.x); p[1] = to_tf32(wv.y);
            p[2] = to_tf32(wv.z); p[3] = to_tf32(wv.w);
        }
        __syncthreads();
#pragma unroll
        for (int k0 = 0; k0 < 32; k0 += 8) {
            uint32_t a0 = xs[wr + g][k0 + t];
            uint32_t a1 = xs[wr + g + 8][k0 + t];
            uint32_t a2 = xs[wr + g][k0 + t + 4];
            uint32_t a3 = xs[wr + g + 8][k0 + t + 4];
#pragma unroll
            for (int nt = 0; nt < 8; nt++) {
                uint32_t b0 = ws[k0 + t][nt * 8 + g];
                uint32_t b1 = ws[k0 + t + 4][nt * 8 + g];
                asm volatile(
                    "mma.sync.aligned.m16n8k8.row.col.f32.tf32.tf32.f32 "
                    "{%0,%1,%2,%3}, {%4,%5,%6,%7}, {%8,%9}, {%0,%1,%2,%3};"
                    : "+f"(c[nt][0]), "+f"(c[nt][1]), "+f"(c[nt][2]), "+f"(c[nt][3])
                    : "r"(a0), "r"(a1), "r"(a2), "r"(a3), "r"(b0), "r"(b1));
            }
        }
        __syncthreads();
    }
    size_t vb = (size_t)v * NN * NH;
    int r0 = row0 + wr + g;
    int r1 = r0 + 8;
#pragma unroll
    for (int nt = 0; nt < 8; nt++) {
        int col = nt * 8 + t * 2;
        if (r0 < NN) *(__half2*)&g_xwh[vb + (size_t)r0 * NH + col] = __floats2half2_rn(c[nt][0], c[nt][1]);
        if (r1 < NN) *(__half2*)&g_xwh[vb + (size_t)r1 * NH + col] = __floats2half2_rn(c[nt][2], c[nt][3]);
    }
}

// conv1 pull + epilogue: 16 lanes per node (half-warp), 4 fp16 features (uint2) per lane.
// Max-of-2 node-loop divergence per warp; one 128B row line per node per edge.
// h = dinv1[node]*sum(part*xw[src]) + dinv1[node]^2*xw[node] + b1
__global__ void k_gather1(const float* __restrict__ b1a, const float* __restrict__ b1b, const float* __restrict__ b1c,
                          const float* __restrict__ W2a, const float* __restrict__ W2b, const float* __restrict__ W2c,
                          float* __restrict__ out_feat) {
    int gtid = blockIdx.x * blockDim.x + threadIdx.x;
    int node = gtid >> 4;
    if (node >= NN) return;
    int q = threadIdx.x & 15;       // features q*4 .. q*4+3

    float fo[4];
#pragma unroll
    for (int i = 0; i < 4; i++) fo[i] = 0.f;
    float dot[3];
#pragma unroll
    for (int v = 0; v < 3; v++) {
        const float* b1 = v == 0 ? b1a : v == 1 ? b1b : b1c;
        const float* W2 = v == 0 ? W2a : v == 1 ? W2b : W2c;
        int beg = g_off[v * (NN + 1) + node];
        int end = g_off[v * (NN + 1) + node + 1];
        const uint32_t* cp = g_csr + v * EMAX;
        const uint2* xw16 = (const uint2*)(g_xwh + (size_t)v * NN * NH);
        float a[4];
#pragma unroll
        for (int i = 0; i < 4; i++) a[i] = 0.f;
#pragma unroll 4
        for (int j = beg; j < end; j++) {
            uint32_t m = cp[j];
            int s = (int)(m & 0xFFFFu);
            float nm = __half2float(__ushort_as_half((unsigned short)(m >> 16)));
            uint2 raw = xw16[(size_t)s * 16 + q];
            float2 f0 = __half22float2(*(__half2*)&raw.x);
            float2 f1 = __half22float2(*(__half2*)&raw.y);
            a[0] += nm * f0.x; a[1] += nm * f0.y;
            a[2] += nm * f1.x; a[3] += nm * f1.y;
        }
        // self loop + dst-degree factor
        float di = g_dinv1[v * NN + node];
        float sn = di * di;
        uint2 sr = xw16[(size_t)node * 16 + q];
        float2 s0 = __half22float2(*(__half2*)&sr.x);
        float2 s1 = __half22float2(*(__half2*)&sr.y);
        float sf[4] = {s0.x, s0.y, s1.x, s1.y};
        float4 bva = *(const float4*)&b1[q * 4];
        float bv[4] = {bva.x, bva.y, bva.z, bva.w};
        float4 w2a = *(const float4*)&W2[q * 4];
        float w2[4] = {w2a.x, w2a.y, w2a.z, w2a.w};
        float dt = 0.f;
#pragma unroll
        for (int i = 0; i < 4; i++) {
            float hv = fmaxf(a[i] * di + sf[i] * sn + bv[i], 0.f);
            fo[i] += hv;
            dt += hv * w2[i];
        }
        dot[v] = dt;
    }
    // reduce dot over the 16 lanes of this node (xor offsets < 16 stay in-group)
#pragma unroll
    for (int o = 8; o > 0; o >>= 1) {
        dot[0] += __shfl_xor_sync(0xFFFFFFFFu, dot[0], o);
        dot[1] += __shfl_xor_sync(0xFFFFFFFFu, dot[1], o);
        dot[2] += __shfl_xor_sync(0xFFFFFFFFu, dot[2], o);
    }
    if (q == 0) {
#pragma unroll
        for (int v = 0; v < 3; v++)
            g_hws[v * NN + node] = dot[v] * g_dinv2[v * NN + node];
    }
    *(float4*)&out_feat[node * NH + q * 4] = make_float4(fo[0], fo[1], fo[2], fo[3]);
}

// conv2 pull
__global__ void k_gather2(const float* __restrict__ b2a, const float* __restrict__ b2b, const float* __restrict__ b2c,
                          float* __restrict__ out) {
    int i = blockIdx.x * blockDim.x + threadIdx.x;
    if (i >= NN) return;
    float acc = 0.f;
#pragma unroll
    for (int v = 0; v < 3; v++) {
        const float* b2 = v == 0 ? b2a : v == 1 ? b2b : b2c;
        int beg = g_off[v * (NN + 1) + i];
        int end = g_off[v * (NN + 1) + i + 1];
        const uint32_t* cp = g_csr + v * EMAX;
        float t = 0.f;
#pragma unroll 8
        for (int j = beg; j < end; j++)
            t += g_hws[v * NN + (int)(cp[j] & 0xFFFFu)];
        float di = g_dinv2[v * NN + i];
        acc += di * t + g_hws[v * NN + i] * di + b2[0];
    }
    out[i] = acc;
}

extern "C" void kernel_launch(void* const* d_in, const int* in_sizes, int n_in,
                              void* d_out, int out_size) {
    const float* x = (const float*)d_in[0];
    const int* e0 = (const int*)d_in[1];
    const int* e1 = (const int*)d_in[2];
    const int* e2 = (const int*)d_in[3];
    const float* w0 = (const float*)d_in[4];
    const float* w1 = (const float*)d_in[5];
    const float* w2 = (const float*)d_in[6];
    const float* W1a = (const float*)d_in[7];
    const float* b1a = (const float*)d_in[8];
    const float* W2a = (const float*)d_in[9];
    const float* b2a = (const float*)d_in[10];
    const float* W1b = (const float*)d_in[11];
    const float* b1b = (const float*)d_in[12];
    const float* W2b = (const float*)d_in[13];
    const float* b2b = (const float*)d_in[14];
    const float* W1c = (const float*)d_in[15];
    const float* b1c = (const float*)d_in[16];
    const float* W2c = (const float*)d_in[17];
    const float* b2c = (const float*)d_in[18];
    float* out = (float*)d_out;
    int E = in_sizes[4];

    // One-time stream/event setup (host-side only; no device memory).
    static cudaStream_t s2 = nullptr;
    static cudaEvent_t evFork = nullptr, evGemm = nullptr;
    if (s2 == nullptr) {
        cudaStreamCreateWithFlags(&s2, cudaStreamNonBlocking);
        cudaEventCreateWithFlags(&evFork, cudaEventDisableTiming);
        cudaEventCreateWithFlags(&evGemm, cudaEventDisableTiming);
    }

    // Fork: GEMM runs on s2 concurrently with the CSR-build chain.
    cudaEventRecord(evFork, 0);
    cudaStreamWaitEvent(s2, evFork, 0);
    dim3 ggemm((NN + 127) / 128, 3);
    k_gemm3<<<ggemm, 256, 0, s2>>>(x, W1a, W1b, W1c);
    cudaEventRecord(evGemm, s2);

    // Edge pipeline on legacy stream
    dim3 gedge((E + 255) / 256, 3);
    k_deg<<<gedge, 256>>>(e0, e1, e2, w0, w1, w2, E);

    dim3 gscan(SCAN_B, 3);
    k_scanA<<<gscan, 256>>>();
    k_scanC<<<gscan, 256>>>(E);

    k_fill<<<gedge, 256>>>(e0, e1, e2, w0, w1, w2, E);

    // Join: gather1 needs both the CSR and g_xwh
    cudaStreamWaitEvent(0, evGemm, 0);

    k_gather1<<<(NN * 16 + 255) / 256, 256>>>(b1a, b1b, b1c, W2a, W2b, W2c, out + NN);

    k_gather2<<<(NN + 255) / 256, 256>>>(b2a, b2b, b2c, out);
}